// round 4
// baseline (speedup 1.0000x reference)
#include <cuda_runtime.h>
#include <math.h>

#define BB   64
#define CC   512
#define HW   784
#define NREG 64
#define TT   56
#define NTILE 14
#define GT   448
// X layout: 16B unit u = (c>>1)*29 + (t>>1); float idx = u*4 + (t&1)*2 + (c&1)
// 256 k2-rows * 29 units * 16B = 118784 bytes
#define XS_FLOATS (256*29*4)
#define XS_BYTES  (XS_FLOATS*4)

// ---------------- scratch ----------------
__device__ __align__(256) float g_scale[CC];
__device__ __align__(256) float g_shift[CC];
__device__ __align__(256) float g_rowsum[BB*CC];
__device__ __align__(256) float g_rowsq [BB*CC];
__device__ __align__(256) float g_a1   [BB*CC];
__device__ __align__(256) float g_att2 [BB*HW];
__device__ __align__(256) float g_srean[(size_t)BB*NREG*HW];
__device__ __align__(256) float g_scorep[BB*NTILE*NREG];
__device__ __align__(256) float g_feat [BB*CC];
__device__ __align__(256) float g_l3[BB];
__device__ __align__(256) float g_ls[BB];

// ---------------- helpers ----------------
__device__ __forceinline__ float wredsum(float v){
    #pragma unroll
    for (int o = 16; o; o >>= 1) v += __shfl_down_sync(0xffffffffu, v, o);
    return v;
}
__device__ __forceinline__ float wredmax(float v){
    #pragma unroll
    for (int o = 16; o; o >>= 1) v = fmaxf(v, __shfl_down_sync(0xffffffffu, v, o));
    return v;
}
__device__ __forceinline__ float blockRedSum256(float v, float* red){
    int lane = threadIdx.x & 31, w = threadIdx.x >> 5;
    v = wredsum(v);
    if (lane == 0) red[w] = v;
    __syncthreads();
    if (threadIdx.x == 0){
        float s = 0.f;
        #pragma unroll
        for (int i = 0; i < 8; i++) s += red[i];
        red[0] = s;
    }
    __syncthreads();
    float r = red[0];
    __syncthreads();
    return r;
}
__device__ __forceinline__ float blockRedMax256(float v, float* red){
    int lane = threadIdx.x & 31, w = threadIdx.x >> 5;
    v = wredmax(v);
    if (lane == 0) red[w] = v;
    __syncthreads();
    if (threadIdx.x == 0){
        float s = red[0];
        #pragma unroll
        for (int i = 1; i < 8; i++) s = fmaxf(s, red[i]);
        red[0] = s;
    }
    __syncthreads();
    float r = red[0];
    __syncthreads();
    return r;
}

#define FMA2(d,a,b) asm("fma.rn.f32x2 %0, %1, %2, %0;" : "+l"(d) : "l"(a), "l"(b))
__device__ __forceinline__ float2 up2(unsigned long long v){
    float2 r; asm("mov.b64 {%0, %1}, %2;" : "=f"(r.x), "=f"(r.y) : "l"(v)); return r;
}
__device__ __forceinline__ int lidx(int c, int t){
    return (((c>>1)*29 + (t>>1))<<2) + ((t&1)<<1) + (c&1);
}

// ---------------- K1a: per-(b,c) row sums ----------------
__global__ void k_rowsum(const float* __restrict__ v){
    int w = (blockIdx.x * blockDim.x + threadIdx.x) >> 5;
    int lane = threadIdx.x & 31;
    if (w >= BB*CC) return;
    const float4* row = (const float4*)(v + (size_t)w * HW);
    float p = 0.f, q = 0.f;
    #pragma unroll
    for (int i = 0; i < 7; i++){
        int idx = lane + i*32;
        if (idx < 196){
            float4 x = row[idx];
            p += x.x + x.y + x.z + x.w;
            q += x.x*x.x + x.y*x.y + x.z*x.z + x.w*x.w;
        }
    }
    p = wredsum(p); q = wredsum(q);
    if (lane == 0){ g_rowsum[w] = p; g_rowsq[w] = q; }
}

// ---------------- K1b: BN scale/shift ----------------
__global__ void k_bnparam(const float* __restrict__ gamma, const float* __restrict__ beta){
    int c = blockIdx.x;
    int b = threadIdx.x;
    __shared__ float sp[BB], sq[BB];
    sp[b] = g_rowsum[b*CC + c];
    sq[b] = g_rowsq [b*CC + c];
    __syncthreads();
    if (b == 0){
        float P = 0.f, Q = 0.f;
        for (int i = 0; i < BB; i++){ P += sp[i]; Q += sq[i]; }
        const float inv = 1.0f / (float)(BB*HW);
        float mu  = P * inv;
        float var = Q * inv - mu*mu;
        float sc  = gamma[c] * rsqrtf(var + 1e-5f);
        g_scale[c] = sc;
        g_shift[c] = beta[c] - mu * sc;
    }
}

// ---------------- K2: a1 = l2norm(t_feature) ----------------
__global__ void k_a1(const float* __restrict__ t){
    int b = blockIdx.x; int tid = threadIdx.x;  // 128
    float s = 0.f;
    for (int c = tid; c < CC; c += 128){ float x = t[b*CC + c]; s += x*x; }
    __shared__ float red[4];
    __shared__ float sinv;
    float ws = wredsum(s);
    if ((tid & 31) == 0) red[tid >> 5] = ws;
    __syncthreads();
    if (tid == 0) sinv = 1.0f / fmaxf(sqrtf(red[0]+red[1]+red[2]+red[3]), 1e-12f);
    __syncthreads();
    for (int c = tid; c < CC; c += 128) g_a1[b*CC + c] = t[b*CC + c] * sinv;
}

// ---------------- K3: fused main pass ----------------
// 448 threads: kq = tid&3 (K quarter), r = tid>>2, tn = r/14 (8 n-rows), tt = r%14 (4 px)
__global__ void __launch_bounds__(GT, 1) k_main(
    const float* __restrict__ v,
    const float* __restrict__ w,
    const float* __restrict__ wb)
{
    extern __shared__ float Xs[];
    __shared__ float pr[8*TT], pa[8*TT], satt[TT], sinv[TT];
    __shared__ float pn[8*TT];
    __shared__ float stile[NREG*NTILE];

    int b    = blockIdx.x / NTILE;
    int tile = blockIdx.x % NTILE;
    int hw0  = tile * TT;
    int tid  = threadIdx.x;

    // ---- fill Xs (padded-linear layout) + fused norm/att partials ----
    {
        int t  = tid % TT;
        int c0 = tid / TT;                  // 0..7
        const float* base = v + (size_t)b*CC*HW + hw0 + t;
        const float* a1b  = g_a1 + b*CC;
        float nr = 0.f, ad = 0.f;
        #pragma unroll 8
        for (int c = c0; c < CC; c += 8){
            float x = base[(size_t)c*HW] * g_scale[c] + g_shift[c];
            Xs[lidx(c,t)] = x;
            nr = fmaf(x, x, nr);
            ad = fmaf(x, a1b[c], ad);
        }
        pr[c0*TT + t] = nr;
        pa[c0*TT + t] = ad;
    }
    __syncthreads();
    if (tid < TT){
        float nr = 0.f, ad = 0.f;
        #pragma unroll
        for (int s = 0; s < 8; s++){ nr += pr[s*TT + tid]; ad += pa[s*TT + tid]; }
        float a = ad / fmaxf(sqrtf(nr), 1e-12f);
        satt[tid] = a;
        g_att2[b*HW + hw0 + tid] = a;
    }

    // ---- GEMM: 8n x 4px per thread, K quarter of 128 ----
    int kq = tid & 3;
    int r  = tid >> 2;           // 0..111
    int tn = r / NTILE;          // 0..7
    int tt = r % NTILE;          // 0..13
    int n0 = tn*8, t0 = tt*4;

    unsigned long long acc[8][4];
    #pragma unroll
    for (int i = 0; i < 8; i++)
        #pragma unroll
        for (int j = 0; j < 4; j++) acc[i][j] = 0ull;

    {
        const ulonglong2* wq[8];
        #pragma unroll
        for (int i = 0; i < 8; i++)
            wq[i] = (const ulonglong2*)(w + (size_t)(n0+i)*CC) + kq*32;

        int s = ((kq*64)*29 + 2*tt) << 2;    // float index of first X unit

        #pragma unroll 4
        for (int k4 = 0; k4 < 32; k4++){
            ulonglong2 wv0 = wq[0][k4], wv1 = wq[1][k4], wv2 = wq[2][k4], wv3 = wq[3][k4];
            ulonglong2 wv4 = wq[4][k4], wv5 = wq[5][k4], wv6 = wq[6][k4], wv7 = wq[7][k4];
            ulonglong2 xa0 = *(const ulonglong2*)(Xs + s);
            ulonglong2 xb0 = *(const ulonglong2*)(Xs + s + 4);
            ulonglong2 xa1 = *(const ulonglong2*)(Xs + s + 116);
            ulonglong2 xb1 = *(const ulonglong2*)(Xs + s + 120);
            s += 232;

            FMA2(acc[0][0], wv0.x, xa0.x); FMA2(acc[0][1], wv0.x, xa0.y);
            FMA2(acc[0][2], wv0.x, xb0.x); FMA2(acc[0][3], wv0.x, xb0.y);
            FMA2(acc[1][0], wv1.x, xa0.x); FMA2(acc[1][1], wv1.x, xa0.y);
            FMA2(acc[1][2], wv1.x, xb0.x); FMA2(acc[1][3], wv1.x, xb0.y);
            FMA2(acc[2][0], wv2.x, xa0.x); FMA2(acc[2][1], wv2.x, xa0.y);
            FMA2(acc[2][2], wv2.x, xb0.x); FMA2(acc[2][3], wv2.x, xb0.y);
            FMA2(acc[3][0], wv3.x, xa0.x); FMA2(acc[3][1], wv3.x, xa0.y);
            FMA2(acc[3][2], wv3.x, xb0.x); FMA2(acc[3][3], wv3.x, xb0.y);
            FMA2(acc[4][0], wv4.x, xa0.x); FMA2(acc[4][1], wv4.x, xa0.y);
            FMA2(acc[4][2], wv4.x, xb0.x); FMA2(acc[4][3], wv4.x, xb0.y);
            FMA2(acc[5][0], wv5.x, xa0.x); FMA2(acc[5][1], wv5.x, xa0.y);
            FMA2(acc[5][2], wv5.x, xb0.x); FMA2(acc[5][3], wv5.x, xb0.y);
            FMA2(acc[6][0], wv6.x, xa0.x); FMA2(acc[6][1], wv6.x, xa0.y);
            FMA2(acc[6][2], wv6.x, xb0.x); FMA2(acc[6][3], wv6.x, xb0.y);
            FMA2(acc[7][0], wv7.x, xa0.x); FMA2(acc[7][1], wv7.x, xa0.y);
            FMA2(acc[7][2], wv7.x, xb0.x); FMA2(acc[7][3], wv7.x, xb0.y);

            FMA2(acc[0][0], wv0.y, xa1.x); FMA2(acc[0][1], wv0.y, xa1.y);
            FMA2(acc[0][2], wv0.y, xb1.x); FMA2(acc[0][3], wv0.y, xb1.y);
            FMA2(acc[1][0], wv1.y, xa1.x); FMA2(acc[1][1], wv1.y, xa1.y);
            FMA2(acc[1][2], wv1.y, xb1.x); FMA2(acc[1][3], wv1.y, xb1.y);
            FMA2(acc[2][0], wv2.y, xa1.x); FMA2(acc[2][1], wv2.y, xa1.y);
            FMA2(acc[2][2], wv2.y, xb1.x); FMA2(acc[2][3], wv2.y, xb1.y);
            FMA2(acc[3][0], wv3.y, xa1.x); FMA2(acc[3][1], wv3.y, xa1.y);
            FMA2(acc[3][2], wv3.y, xb1.x); FMA2(acc[3][3], wv3.y, xb1.y);
            FMA2(acc[4][0], wv4.y, xa1.x); FMA2(acc[4][1], wv4.y, xa1.y);
            FMA2(acc[4][2], wv4.y, xb1.x); FMA2(acc[4][3], wv4.y, xb1.y);
            FMA2(acc[5][0], wv5.y, xa1.x); FMA2(acc[5][1], wv5.y, xa1.y);
            FMA2(acc[5][2], wv5.y, xb1.x); FMA2(acc[5][3], wv5.y, xb1.y);
            FMA2(acc[6][0], wv6.y, xa1.x); FMA2(acc[6][1], wv6.y, xa1.y);
            FMA2(acc[6][2], wv6.y, xb1.x); FMA2(acc[6][3], wv6.y, xb1.y);
            FMA2(acc[7][0], wv7.y, xa1.x); FMA2(acc[7][1], wv7.y, xa1.y);
            FMA2(acc[7][2], wv7.y, xb1.x); FMA2(acc[7][3], wv7.y, xb1.y);
        }
    }

    // ---- combine K quarters, normalize, store ----
    __syncthreads();                        // all GEMM reads of Xs done
    float* comb = Xs;                       // 3 * [64][56] partials

    float sres[8][4];
    #pragma unroll
    for (int i = 0; i < 8; i++)
        #pragma unroll
        for (int j = 0; j < 4; j++){
            float2 f = up2(acc[i][j]);
            sres[i][j] = f.x + f.y;
        }

    if (kq){
        float* cb = comb + (kq-1)*NREG*TT;
        #pragma unroll
        for (int i = 0; i < 8; i++){
            float4 o = make_float4(sres[i][0], sres[i][1], sres[i][2], sres[i][3]);
            *(float4*)&cb[(n0+i)*TT + t0] = o;
        }
    }
    __syncthreads();
    if (kq == 0){
        #pragma unroll
        for (int i = 0; i < 8; i++){
            float bi = wb[n0+i];
            int rw = (n0+i)*TT + t0;
            #pragma unroll
            for (int j = 0; j < 4; j++)
                sres[i][j] += comb[rw+j] + comb[NREG*TT + rw+j] + comb[2*NREG*TT + rw+j] + bi;
        }
        #pragma unroll
        for (int j = 0; j < 4; j++){
            float ss = 0.f;
            #pragma unroll
            for (int i = 0; i < 8; i++) ss = fmaf(sres[i][j], sres[i][j], ss);
            pn[tn*TT + t0 + j] = ss;
        }
    }
    __syncthreads();
    if (tid < TT){
        float ss = 0.f;
        #pragma unroll
        for (int g = 0; g < 8; g++) ss += pn[g*TT + tid];
        sinv[tid] = 1.0f / fmaxf(sqrtf(ss), 1e-12f);
    }
    __syncthreads();
    if (kq == 0){
        float* outb = g_srean + ((size_t)b*NREG)*HW + hw0;
        float a0 = satt[t0], a1v = satt[t0+1], a2 = satt[t0+2], a3 = satt[t0+3];
        float i0 = sinv[t0], i1 = sinv[t0+1], i2 = sinv[t0+2], i3 = sinv[t0+3];
        #pragma unroll
        for (int i = 0; i < 8; i++){
            float4 o;
            o.x = sres[i][0]*i0; o.y = sres[i][1]*i1;
            o.z = sres[i][2]*i2; o.w = sres[i][3]*i3;
            *(float4*)&outb[(size_t)(n0+i)*HW + t0] = o;
            stile[(n0+i)*NTILE + tt] = o.x*a0 + o.y*a1v + o.z*a2 + o.w*a3;
        }
    }
    __syncthreads();
    if (tid < NREG){
        float q = 0.f;
        #pragma unroll
        for (int tl = 0; tl < NTILE; tl++) q += stile[tid*NTILE + tl];
        g_scorep[(b*NTILE + tile)*NREG + tid] = q;
    }
}

// ---------------- K5: feat = pooled @ fc1_w^T + fc1_b ----------------
#define PS 513
__global__ void k_feat(const float* __restrict__ fw, const float* __restrict__ fb){
    extern __shared__ float sm[];
    float* pooled = sm;
    float* ws     = sm + BB*PS;
    int tid = threadIdx.x;           // 256
    int o0 = blockIdx.x * 8;

    for (int idx = tid; idx < BB*CC; idx += 256){
        int bb = idx >> 9, cc = idx & 511;
        pooled[bb*PS + cc] = g_rowsum[idx] * (1.0f/(float)HW) * g_scale[cc] + g_shift[cc];
    }
    for (int idx = tid; idx < 8*CC; idx += 256){
        int oo = idx >> 9, cc = idx & 511;
        ws[oo*PS + cc] = fw[(size_t)(o0+oo)*CC + cc];
    }
    __syncthreads();

    #pragma unroll
    for (int rr = 0; rr < 2; rr++){
        int p  = tid*2 + rr;
        int bb = p >> 3, oo = p & 7;
        float s = 0.f;
        #pragma unroll 8
        for (int k = 0; k < CC; k++) s = fmaf(pooled[bb*PS + k], ws[oo*PS + k], s);
        g_feat[bb*CC + (o0+oo)] = s + fb[o0+oo];
    }
}

// ---------------- K6: per-batch stats + loss terms ----------------
__global__ void k_loss(){
    int b = blockIdx.x; int tid = threadIdx.x;  // 256
    __shared__ float ssc[NREG];
    __shared__ int s_nmax;
    __shared__ float red[8];
    if (tid < NREG){
        float sv = 0.f;
        #pragma unroll
        for (int tl = 0; tl < NTILE; tl++) sv += g_scorep[(b*NTILE + tl)*NREG + tid];
        ssc[tid] = sv;
    }
    __syncthreads();
    if (tid == 0){
        float m = 0.f;
        for (int n = 0; n < NREG; n++) m += ssc[n];
        m *= (1.0f/NREG);
        float bmax = ssc[0]; int imax = 0;
        float sp = 0.f, sq = 0.f;
        for (int n = 0; n < NREG; n++){
            float x = ssc[n];
            if (x > bmax){ bmax = x; imax = n; }
            if (x > m) sp += x; else sq += x;
        }
        sp *= (1.0f/NREG); sq *= (1.0f/NREG);
        float d = sq - sp;
        g_l3[b] = (d > 20.0f) ? d : log1pf(expf(d));
        s_nmax = imax;
    }
    __syncthreads();

    const float* pl = g_att2 + b*HW;
    const float* ql = g_srean + ((size_t)b*NREG + s_nmax)*HW;
    const float qs = 1.0f/(float)NREG;

    float mp = -1e30f, mq = -1e30f;
    for (int h = tid; h < HW; h += 256){
        mp = fmaxf(mp, pl[h]);
        mq = fmaxf(mq, ql[h]*qs);
    }
    mp = blockRedMax256(mp, red);
    mq = blockRedMax256(mq, red);

    float ep = 0.f, eq = 0.f;
    for (int h = tid; h < HW; h += 256){
        ep += expf(pl[h] - mp);
        eq += expf(ql[h]*qs - mq);
    }
    ep = blockRedSum256(ep, red);
    eq = blockRedSum256(eq, red);
    float lsep = mp + logf(ep);
    float lseq = mq + logf(eq);

    float S = 0.f;
    for (int h = tid; h < HW; h += 256){
        float lp = pl[h] - lsep;
        float lq = ql[h]*qs - lseq;
        float p  = expf(lp);
        float q  = expf(lq);
        float lm = logf(0.5f*(p + q));
        S += p*(lp - lm) + q*(lq - lm);
    }
    S = blockRedSum256(S, red);
    if (tid == 0) g_ls[b] = S;
}

// ---------------- K7: dual_sim ----------------
__global__ void k_dual(float* __restrict__ out){
    int b = blockIdx.x; int tid = threadIdx.x;  // 128
    __shared__ float fr[CC];
    __shared__ float red[4];
    __shared__ float sinvb;
    float ss = 0.f;
    for (int c = tid; c < CC; c += 128){ float x = g_feat[b*CC + c]; fr[c] = x; ss += x*x; }
    ss = wredsum(ss);
    if ((tid & 31) == 0) red[tid >> 5] = ss;
    __syncthreads();
    if (tid == 0) sinvb = 1.0f / fmaxf(sqrtf(red[0]+red[1]+red[2]+red[3]), 1e-12f);
    __syncthreads();
    int warp = tid >> 5, lane = tid & 31;
    for (int j = warp; j < BB; j += 4){
        const float* a = g_a1 + j*CC;
        float s = 0.f;
        for (int c = lane; c < CC; c += 32) s += fr[c] * a[c];
        s = wredsum(s);
        if (lane == 0) out[b*BB + j] = s * sinvb;
    }
}

// ---------------- K8: final scalar ----------------
__global__ void k_final(float* __restrict__ out, int li){
    int t = threadIdx.x;  // 64
    __shared__ float r3[BB], rls[BB];
    r3[t] = g_l3[t]; rls[t] = g_ls[t];
    __syncthreads();
    if (t == 0){
        float a = 0.f, c2 = 0.f;
        for (int i = 0; i < BB; i++){ a += r3[i]; c2 += rls[i]; }
        float loss3 = a / (float)BB;
        float loss2 = 0.5f * c2 / (float)BB;
        out[li] = 0.1f*loss3 + 0.1f*loss2;
    }
}

// ---------------- launcher ----------------
extern "C" void kernel_launch(void* const* d_in, const int* in_sizes, int n_in,
                              void* d_out, int out_size){
    const float* v     = (const float*)d_in[0];
    const float* t     = (const float*)d_in[1];
    const float* cw    = (const float*)d_in[2];
    const float* cb    = (const float*)d_in[3];
    const float* gamma = (const float*)d_in[4];
    const float* beta  = (const float*)d_in[5];
    const float* fw    = (const float*)d_in[6];
    const float* fb    = (const float*)d_in[7];
    float* out = (float*)d_out;

    cudaFuncSetAttribute(k_main, cudaFuncAttributeMaxDynamicSharedMemorySize, XS_BYTES);
    cudaFuncSetAttribute(k_feat, cudaFuncAttributeMaxDynamicSharedMemorySize, (BB*PS + 8*PS)*4);

    k_rowsum<<<(BB*CC)/8, 256>>>(v);
    k_bnparam<<<CC, 64>>>(gamma, beta);
    k_a1<<<BB, 128>>>(t);
    k_main<<<BB*NTILE, GT, XS_BYTES>>>(v, cw, cb);
    k_feat<<<64, 256, (BB*PS + 8*PS)*4>>>(fw, fb);
    k_loss<<<BB, 256>>>();
    k_dual<<<BB, 128>>>(out);
    int li = (out_size > 4096) ? 4096 : (out_size - 1);
    k_final<<<1, 64>>>(out, li);
}

// round 5
// speedup vs baseline: 1.6923x; 1.6923x over previous
#include <cuda_runtime.h>
#include <math.h>

#define BB   64
#define CC   512
#define HW   784
#define NREG 64
#define TT   56
#define NTILE 14
#define GT   448
// X layout: 16B unit u = tp*257 + k2  (tp = pixel pair 0..27, k2 = K pair 0..255)
// float idx = 4u + (t&1)*2 + (c&1). Max fidx = (27*257+255)*4+3 = 28779.
#define XS_FLOATS 28780
#define XS_BYTES  (XS_FLOATS*4)
#define OFF14     (14*257*4)   // float offset between pair tt and pair tt+14

// ---------------- scratch ----------------
__device__ __align__(256) float g_scale[CC];
__device__ __align__(256) float g_shift[CC];
__device__ __align__(256) float g_rowsum[BB*CC];
__device__ __align__(256) float g_rowsq [BB*CC];
__device__ __align__(256) float g_a1   [BB*CC];
__device__ __align__(256) float g_att2 [BB*HW];
__device__ __align__(256) float g_srean[(size_t)BB*NREG*HW];
__device__ __align__(256) float g_scorep[BB*NTILE*NREG];
__device__ __align__(256) float g_feat [BB*CC];
__device__ __align__(256) float g_l3[BB];
__device__ __align__(256) float g_ls[BB];

// ---------------- helpers ----------------
__device__ __forceinline__ float wredsum(float v){
    #pragma unroll
    for (int o = 16; o; o >>= 1) v += __shfl_down_sync(0xffffffffu, v, o);
    return v;
}
__device__ __forceinline__ float wredmax(float v){
    #pragma unroll
    for (int o = 16; o; o >>= 1) v = fmaxf(v, __shfl_down_sync(0xffffffffu, v, o));
    return v;
}
__device__ __forceinline__ float blockRedSum256(float v, float* red){
    int lane = threadIdx.x & 31, w = threadIdx.x >> 5;
    v = wredsum(v);
    if (lane == 0) red[w] = v;
    __syncthreads();
    if (threadIdx.x == 0){
        float s = 0.f;
        #pragma unroll
        for (int i = 0; i < 8; i++) s += red[i];
        red[0] = s;
    }
    __syncthreads();
    float r = red[0];
    __syncthreads();
    return r;
}
__device__ __forceinline__ float blockRedMax256(float v, float* red){
    int lane = threadIdx.x & 31, w = threadIdx.x >> 5;
    v = wredmax(v);
    if (lane == 0) red[w] = v;
    __syncthreads();
    if (threadIdx.x == 0){
        float s = red[0];
        #pragma unroll
        for (int i = 1; i < 8; i++) s = fmaxf(s, red[i]);
        red[0] = s;
    }
    __syncthreads();
    float r = red[0];
    __syncthreads();
    return r;
}

#define FMA2(d,a,b) asm("fma.rn.f32x2 %0, %1, %2, %0;" : "+l"(d) : "l"(a), "l"(b))
__device__ __forceinline__ float2 up2(unsigned long long v){
    float2 r; asm("mov.b64 {%0, %1}, %2;" : "=f"(r.x), "=f"(r.y) : "l"(v)); return r;
}
__device__ __forceinline__ int lidx(int c, int t){
    return (((t>>1)*257 + (c>>1))<<2) + ((t&1)<<1) + (c&1);
}

// ---------------- K1a: per-(b,c) row sums ----------------
__global__ void k_rowsum(const float* __restrict__ v){
    int w = (blockIdx.x * blockDim.x + threadIdx.x) >> 5;
    int lane = threadIdx.x & 31;
    if (w >= BB*CC) return;
    const float4* row = (const float4*)(v + (size_t)w * HW);
    float p = 0.f, q = 0.f;
    #pragma unroll
    for (int i = 0; i < 7; i++){
        int idx = lane + i*32;
        if (idx < 196){
            float4 x = row[idx];
            p += x.x + x.y + x.z + x.w;
            q += x.x*x.x + x.y*x.y + x.z*x.z + x.w*x.w;
        }
    }
    p = wredsum(p); q = wredsum(q);
    if (lane == 0){ g_rowsum[w] = p; g_rowsq[w] = q; }
}

// ---------------- K1b: BN scale/shift ----------------
__global__ void k_bnparam(const float* __restrict__ gamma, const float* __restrict__ beta){
    int c = blockIdx.x;
    int b = threadIdx.x;
    __shared__ float sp[BB], sq[BB];
    sp[b] = g_rowsum[b*CC + c];
    sq[b] = g_rowsq [b*CC + c];
    __syncthreads();
    if (b == 0){
        float P = 0.f, Q = 0.f;
        for (int i = 0; i < BB; i++){ P += sp[i]; Q += sq[i]; }
        const float inv = 1.0f / (float)(BB*HW);
        float mu  = P * inv;
        float var = Q * inv - mu*mu;
        float sc  = gamma[c] * rsqrtf(var + 1e-5f);
        g_scale[c] = sc;
        g_shift[c] = beta[c] - mu * sc;
    }
}

// ---------------- K2: a1 = l2norm(t_feature) ----------------
__global__ void k_a1(const float* __restrict__ t){
    int b = blockIdx.x; int tid = threadIdx.x;  // 128
    float s = 0.f;
    for (int c = tid; c < CC; c += 128){ float x = t[b*CC + c]; s += x*x; }
    __shared__ float red[4];
    __shared__ float sinv;
    float ws = wredsum(s);
    if ((tid & 31) == 0) red[tid >> 5] = ws;
    __syncthreads();
    if (tid == 0) sinv = 1.0f / fmaxf(sqrtf(red[0]+red[1]+red[2]+red[3]), 1e-12f);
    __syncthreads();
    for (int c = tid; c < CC; c += 128) g_a1[b*CC + c] = t[b*CC + c] * sinv;
}

// ---------------- K3: fused main pass ----------------
// 448 threads. kq = tid/112 (K quarter, warp-coherent); r = tid%112;
// tn = r/14 -> 8 n-rows; tt = r%14 -> pixels {2tt, 2tt+1, 2tt+28, 2tt+29}.
__global__ void __launch_bounds__(GT) k_main(
    const float* __restrict__ v,
    const float* __restrict__ w,
    const float* __restrict__ wb)
{
    extern __shared__ float Xs[];
    __shared__ float pr[8*TT], pa[8*TT], satt[TT], sinv[TT];
    __shared__ float pn[8*TT];
    __shared__ float stile[NREG*NTILE];

    int b    = blockIdx.x / NTILE;
    int tile = blockIdx.x % NTILE;
    int hw0  = tile * TT;
    int tid  = threadIdx.x;

    // ---- fill Xs + fused norm/att partials ----
    {
        int t  = tid % TT;
        int c0 = tid / TT;                  // 0..7
        const float* base = v + (size_t)b*CC*HW + hw0 + t;
        const float* a1b  = g_a1 + b*CC;
        float nr = 0.f, ad = 0.f;
        int fx = lidx(c0, t);               // step of c by 8 -> fidx += 16
        #pragma unroll 8
        for (int c = c0; c < CC; c += 8){
            float x = base[(size_t)c*HW] * g_scale[c] + g_shift[c];
            Xs[fx] = x;
            fx += 16;
            nr = fmaf(x, x, nr);
            ad = fmaf(x, a1b[c], ad);
        }
        pr[c0*TT + t] = nr;
        pa[c0*TT + t] = ad;
    }
    __syncthreads();
    if (tid < TT){
        float nr = 0.f, ad = 0.f;
        #pragma unroll
        for (int s = 0; s < 8; s++){ nr += pr[s*TT + tid]; ad += pa[s*TT + tid]; }
        float a = ad / fmaxf(sqrtf(nr), 1e-12f);
        satt[tid] = a;
        g_att2[b*HW + hw0 + tid] = a;
    }

    // ---- GEMM ----
    int kq = tid / 112;
    int r  = tid % 112;
    int tn = r / NTILE;          // 0..7
    int tt = r % NTILE;          // 0..13
    int n0 = tn*8;
    int p0 = 2*tt;               // first pixel; second group at p0+28

    unsigned long long acc[8][4];
    #pragma unroll
    for (int i = 0; i < 8; i++)
        #pragma unroll
        for (int j = 0; j < 4; j++) acc[i][j] = 0ull;

    {
        const ulonglong2* wp = (const ulonglong2*)w + n0*128 + kq*32;
        int s = (tt*257 + kq*64) << 2;       // float index of unit (pair tt, k2=kq*64)

        #pragma unroll 2
        for (int k4 = 0; k4 < 32; k4++){
            ulonglong2 xa0 = *(const ulonglong2*)(Xs + s);             // pair tt,   k2
            ulonglong2 xa1 = *(const ulonglong2*)(Xs + s + 4);         // pair tt,   k2+1
            ulonglong2 xb0 = *(const ulonglong2*)(Xs + s + OFF14);     // pair tt+14,k2
            ulonglong2 xb1 = *(const ulonglong2*)(Xs + s + OFF14 + 4); // pair tt+14,k2+1
            s += 8;

            {
                ulonglong2 wv0 = wp[k4 + 0*128];
                ulonglong2 wv1 = wp[k4 + 1*128];
                ulonglong2 wv2 = wp[k4 + 2*128];
                ulonglong2 wv3 = wp[k4 + 3*128];
                FMA2(acc[0][0], wv0.x, xa0.x); FMA2(acc[0][1], wv0.x, xa0.y);
                FMA2(acc[0][2], wv0.x, xb0.x); FMA2(acc[0][3], wv0.x, xb0.y);
                FMA2(acc[0][0], wv0.y, xa1.x); FMA2(acc[0][1], wv0.y, xa1.y);
                FMA2(acc[0][2], wv0.y, xb1.x); FMA2(acc[0][3], wv0.y, xb1.y);
                FMA2(acc[1][0], wv1.x, xa0.x); FMA2(acc[1][1], wv1.x, xa0.y);
                FMA2(acc[1][2], wv1.x, xb0.x); FMA2(acc[1][3], wv1.x, xb0.y);
                FMA2(acc[1][0], wv1.y, xa1.x); FMA2(acc[1][1], wv1.y, xa1.y);
                FMA2(acc[1][2], wv1.y, xb1.x); FMA2(acc[1][3], wv1.y, xb1.y);
                FMA2(acc[2][0], wv2.x, xa0.x); FMA2(acc[2][1], wv2.x, xa0.y);
                FMA2(acc[2][2], wv2.x, xb0.x); FMA2(acc[2][3], wv2.x, xb0.y);
                FMA2(acc[2][0], wv2.y, xa1.x); FMA2(acc[2][1], wv2.y, xa1.y);
                FMA2(acc[2][2], wv2.y, xb1.x); FMA2(acc[2][3], wv2.y, xb1.y);
                FMA2(acc[3][0], wv3.x, xa0.x); FMA2(acc[3][1], wv3.x, xa0.y);
                FMA2(acc[3][2], wv3.x, xb0.x); FMA2(acc[3][3], wv3.x, xb0.y);
                FMA2(acc[3][0], wv3.y, xa1.x); FMA2(acc[3][1], wv3.y, xa1.y);
                FMA2(acc[3][2], wv3.y, xb1.x); FMA2(acc[3][3], wv3.y, xb1.y);
            }
            {
                ulonglong2 wv4 = wp[k4 + 4*128];
                ulonglong2 wv5 = wp[k4 + 5*128];
                ulonglong2 wv6 = wp[k4 + 6*128];
                ulonglong2 wv7 = wp[k4 + 7*128];
                FMA2(acc[4][0], wv4.x, xa0.x); FMA2(acc[4][1], wv4.x, xa0.y);
                FMA2(acc[4][2], wv4.x, xb0.x); FMA2(acc[4][3], wv4.x, xb0.y);
                FMA2(acc[4][0], wv4.y, xa1.x); FMA2(acc[4][1], wv4.y, xa1.y);
                FMA2(acc[4][2], wv4.y, xb1.x); FMA2(acc[4][3], wv4.y, xb1.y);
                FMA2(acc[5][0], wv5.x, xa0.x); FMA2(acc[5][1], wv5.x, xa0.y);
                FMA2(acc[5][2], wv5.x, xb0.x); FMA2(acc[5][3], wv5.x, xb0.y);
                FMA2(acc[5][0], wv5.y, xa1.x); FMA2(acc[5][1], wv5.y, xa1.y);
                FMA2(acc[5][2], wv5.y, xb1.x); FMA2(acc[5][3], wv5.y, xb1.y);
                FMA2(acc[6][0], wv6.x, xa0.x); FMA2(acc[6][1], wv6.x, xa0.y);
                FMA2(acc[6][2], wv6.x, xb0.x); FMA2(acc[6][3], wv6.x, xb0.y);
                FMA2(acc[6][0], wv6.y, xa1.x); FMA2(acc[6][1], wv6.y, xa1.y);
                FMA2(acc[6][2], wv6.y, xb1.x); FMA2(acc[6][3], wv6.y, xb1.y);
                FMA2(acc[7][0], wv7.x, xa0.x); FMA2(acc[7][1], wv7.x, xa0.y);
                FMA2(acc[7][2], wv7.x, xb0.x); FMA2(acc[7][3], wv7.x, xb0.y);
                FMA2(acc[7][0], wv7.y, xa1.x); FMA2(acc[7][1], wv7.y, xa1.y);
                FMA2(acc[7][2], wv7.y, xb1.x); FMA2(acc[7][3], wv7.y, xb1.y);
            }
        }
    }

    // ---- combine K quarters, normalize, store ----
    __syncthreads();                        // all GEMM reads of Xs done
    float* comb = Xs;                       // 3 * [64][56] partials

    float sres[8][4];
    #pragma unroll
    for (int i = 0; i < 8; i++)
        #pragma unroll
        for (int j = 0; j < 4; j++){
            float2 f = up2(acc[i][j]);
            sres[i][j] = f.x + f.y;
        }

    if (kq){
        float* cb = comb + (kq-1)*NREG*TT;
        #pragma unroll
        for (int i = 0; i < 8; i++){
            int rw = (n0+i)*TT;
            *(float2*)&cb[rw + p0]      = make_float2(sres[i][0], sres[i][1]);
            *(float2*)&cb[rw + p0 + 28] = make_float2(sres[i][2], sres[i][3]);
        }
    }
    __syncthreads();
    if (kq == 0){
        #pragma unroll
        for (int i = 0; i < 8; i++){
            float bi = wb[n0+i];
            int rw = (n0+i)*TT;
            sres[i][0] += comb[rw+p0]    + comb[NREG*TT + rw+p0]    + comb[2*NREG*TT + rw+p0]    + bi;
            sres[i][1] += comb[rw+p0+1]  + comb[NREG*TT + rw+p0+1]  + comb[2*NREG*TT + rw+p0+1]  + bi;
            sres[i][2] += comb[rw+p0+28] + comb[NREG*TT + rw+p0+28] + comb[2*NREG*TT + rw+p0+28] + bi;
            sres[i][3] += comb[rw+p0+29] + comb[NREG*TT + rw+p0+29] + comb[2*NREG*TT + rw+p0+29] + bi;
        }
        float ss0 = 0.f, ss1 = 0.f, ss2 = 0.f, ss3 = 0.f;
        #pragma unroll
        for (int i = 0; i < 8; i++){
            ss0 = fmaf(sres[i][0], sres[i][0], ss0);
            ss1 = fmaf(sres[i][1], sres[i][1], ss1);
            ss2 = fmaf(sres[i][2], sres[i][2], ss2);
            ss3 = fmaf(sres[i][3], sres[i][3], ss3);
        }
        *(float2*)&pn[tn*TT + p0]      = make_float2(ss0, ss1);
        *(float2*)&pn[tn*TT + p0 + 28] = make_float2(ss2, ss3);
    }
    __syncthreads();
    if (tid < TT){
        float ss = 0.f;
        #pragma unroll
        for (int g = 0; g < 8; g++) ss += pn[g*TT + tid];
        sinv[tid] = 1.0f / fmaxf(sqrtf(ss), 1e-12f);
    }
    __syncthreads();
    if (kq == 0){
        float* outb = g_srean + ((size_t)b*NREG)*HW + hw0;
        float a0 = satt[p0], a1v = satt[p0+1], a2 = satt[p0+28], a3 = satt[p0+29];
        float i0 = sinv[p0], i1 = sinv[p0+1], i2 = sinv[p0+28], i3 = sinv[p0+29];
        #pragma unroll
        for (int i = 0; i < 8; i++){
            float o0 = sres[i][0]*i0, o1 = sres[i][1]*i1;
            float o2 = sres[i][2]*i2, o3 = sres[i][3]*i3;
            float* orow = outb + (size_t)(n0+i)*HW;
            *(float2*)&orow[p0]      = make_float2(o0, o1);
            *(float2*)&orow[p0 + 28] = make_float2(o2, o3);
            stile[(n0+i)*NTILE + tt] = o0*a0 + o1*a1v + o2*a2 + o3*a3;
        }
    }
    __syncthreads();
    if (tid < NREG){
        float q = 0.f;
        #pragma unroll
        for (int tl = 0; tl < NTILE; tl++) q += stile[tid*NTILE + tl];
        g_scorep[(b*NTILE + tile)*NREG + tid] = q;
    }
}

// ---------------- K5: feat = pooled @ fc1_w^T + fc1_b ----------------
#define PS 513
__global__ void k_feat(const float* __restrict__ fw, const float* __restrict__ fb){
    extern __shared__ float sm[];
    float* pooled = sm;
    float* ws     = sm + BB*PS;
    int tid = threadIdx.x;           // 256
    int o0 = blockIdx.x * 8;

    for (int idx = tid; idx < BB*CC; idx += 256){
        int bb = idx >> 9, cc = idx & 511;
        pooled[bb*PS + cc] = g_rowsum[idx] * (1.0f/(float)HW) * g_scale[cc] + g_shift[cc];
    }
    for (int idx = tid; idx < 8*CC; idx += 256){
        int oo = idx >> 9, cc = idx & 511;
        ws[oo*PS + cc] = fw[(size_t)(o0+oo)*CC + cc];
    }
    __syncthreads();

    #pragma unroll
    for (int rr = 0; rr < 2; rr++){
        int p  = tid*2 + rr;
        int bb = p >> 3, oo = p & 7;
        float s = 0.f;
        #pragma unroll 8
        for (int k = 0; k < CC; k++) s = fmaf(pooled[bb*PS + k], ws[oo*PS + k], s);
        g_feat[bb*CC + (o0+oo)] = s + fb[o0+oo];
    }
}

// ---------------- K6: per-batch stats + loss terms ----------------
__global__ void k_loss(){
    int b = blockIdx.x; int tid = threadIdx.x;  // 256
    __shared__ float ssc[NREG];
    __shared__ int s_nmax;
    __shared__ float red[8];
    if (tid < NREG){
        float sv = 0.f;
        #pragma unroll
        for (int tl = 0; tl < NTILE; tl++) sv += g_scorep[(b*NTILE + tl)*NREG + tid];
        ssc[tid] = sv;
    }
    __syncthreads();
    if (tid == 0){
        float m = 0.f;
        for (int n = 0; n < NREG; n++) m += ssc[n];
        m *= (1.0f/NREG);
        float bmax = ssc[0]; int imax = 0;
        float sp = 0.f, sq = 0.f;
        for (int n = 0; n < NREG; n++){
            float x = ssc[n];
            if (x > bmax){ bmax = x; imax = n; }
            if (x > m) sp += x; else sq += x;
        }
        sp *= (1.0f/NREG); sq *= (1.0f/NREG);
        float d = sq - sp;
        g_l3[b] = (d > 20.0f) ? d : log1pf(expf(d));
        s_nmax = imax;
    }
    __syncthreads();

    const float* pl = g_att2 + b*HW;
    const float* ql = g_srean + ((size_t)b*NREG + s_nmax)*HW;
    const float qs = 1.0f/(float)NREG;

    float mp = -1e30f, mq = -1e30f;
    for (int h = tid; h < HW; h += 256){
        mp = fmaxf(mp, pl[h]);
        mq = fmaxf(mq, ql[h]*qs);
    }
    mp = blockRedMax256(mp, red);
    mq = blockRedMax256(mq, red);

    float ep = 0.f, eq = 0.f;
    for (int h = tid; h < HW; h += 256){
        ep += expf(pl[h] - mp);
        eq += expf(ql[h]*qs - mq);
    }
    ep = blockRedSum256(ep, red);
    eq = blockRedSum256(eq, red);
    float lsep = mp + logf(ep);
    float lseq = mq + logf(eq);

    float S = 0.f;
    for (int h = tid; h < HW; h += 256){
        float lp = pl[h] - lsep;
        float lq = ql[h]*qs - lseq;
        float p  = expf(lp);
        float q  = expf(lq);
        float lm = logf(0.5f*(p + q));
        S += p*(lp - lm) + q*(lq - lm);
    }
    S = blockRedSum256(S, red);
    if (tid == 0) g_ls[b] = S;
}

// ---------------- K7: dual_sim ----------------
__global__ void k_dual(float* __restrict__ out){
    int b = blockIdx.x; int tid = threadIdx.x;  // 128
    __shared__ float fr[CC];
    __shared__ float red[4];
    __shared__ float sinvb;
    float ss = 0.f;
    for (int c = tid; c < CC; c += 128){ float x = g_feat[b*CC + c]; fr[c] = x; ss += x*x; }
    ss = wredsum(ss);
    if ((tid & 31) == 0) red[tid >> 5] = ss;
    __syncthreads();
    if (tid == 0) sinvb = 1.0f / fmaxf(sqrtf(red[0]+red[1]+red[2]+red[3]), 1e-12f);
    __syncthreads();
    int warp = tid >> 5, lane = tid & 31;
    for (int j = warp; j < BB; j += 4){
        const float* a = g_a1 + j*CC;
        float s = 0.f;
        for (int c = lane; c < CC; c += 32) s += fr[c] * a[c];
        s = wredsum(s);
        if (lane == 0) out[b*BB + j] = s * sinvb;
    }
}

// ---------------- K8: final scalar ----------------
__global__ void k_final(float* __restrict__ out, int li){
    int t = threadIdx.x;  // 64
    __shared__ float r3[BB], rls[BB];
    r3[t] = g_l3[t]; rls[t] = g_ls[t];
    __syncthreads();
    if (t == 0){
        float a = 0.f, c2 = 0.f;
        for (int i = 0; i < BB; i++){ a += r3[i]; c2 += rls[i]; }
        float loss3 = a / (float)BB;
        float loss2 = 0.5f * c2 / (float)BB;
        out[li] = 0.1f*loss3 + 0.1f*loss2;
    }
}

// ---------------- launcher ----------------
extern "C" void kernel_launch(void* const* d_in, const int* in_sizes, int n_in,
                              void* d_out, int out_size){
    const float* v     = (const float*)d_in[0];
    const float* t     = (const float*)d_in[1];
    const float* cw    = (const float*)d_in[2];
    const float* cb    = (const float*)d_in[3];
    const float* gamma = (const float*)d_in[4];
    const float* beta  = (const float*)d_in[5];
    const float* fw    = (const float*)d_in[6];
    const float* fb    = (const float*)d_in[7];
    float* out = (float*)d_out;

    cudaFuncSetAttribute(k_main, cudaFuncAttributeMaxDynamicSharedMemorySize, XS_BYTES);
    cudaFuncSetAttribute(k_feat, cudaFuncAttributeMaxDynamicSharedMemorySize, (BB*PS + 8*PS)*4);

    k_rowsum<<<(BB*CC)/8, 256>>>(v);
    k_bnparam<<<CC, 64>>>(gamma, beta);
    k_a1<<<BB, 128>>>(t);
    k_main<<<BB*NTILE, GT, XS_BYTES>>>(v, cw, cb);
    k_feat<<<64, 256, (BB*PS + 8*PS)*4>>>(fw, fb);
    k_loss<<<BB, 256>>>();
    k_dual<<<BB, 128>>>(out);
    int li = (out_size > 4096) ? 4096 : (out_size - 1);
    k_final<<<1, 64>>>(out, li);
}

// round 6
// speedup vs baseline: 1.7723x; 1.0472x over previous
#include <cuda_runtime.h>
#include <math.h>

#define BB   64
#define CC   512
#define HW   784
#define NREG 64
#define TT   56
#define NTILE 14
#define GT   448
// X layout: 16B unit u = tp*257 + k2  (tp = pixel pair 0..27, k2 = K pair 0..255)
// float idx = 4u + (t&1)*2 + (c&1). Max fidx = (27*257+255)*4+3 = 28779.
#define XS_FLOATS 28780
#define XS_BYTES  (XS_FLOATS*4)
#define OFF14     (14*257*4)   // float offset between pair tt and pair tt+14

// ---------------- scratch ----------------
__device__ __align__(256) float g_scale[CC];
__device__ __align__(256) float g_shift[CC];
__device__ __align__(256) float g_rowsum[BB*CC];
__device__ __align__(256) float g_rowsq [BB*CC];
__device__ __align__(256) float g_a1   [BB*CC];
__device__ __align__(256) float g_att2 [BB*HW];
__device__ __align__(256) float g_srean[(size_t)BB*NREG*HW];
__device__ __align__(256) float g_scorep[BB*NTILE*NREG];
__device__ __align__(256) float g_feat [BB*CC];
__device__ __align__(256) float g_l3[BB];
__device__ __align__(256) float g_ls[BB];

// ---------------- helpers ----------------
__device__ __forceinline__ float wredsum(float v){
    #pragma unroll
    for (int o = 16; o; o >>= 1) v += __shfl_down_sync(0xffffffffu, v, o);
    return v;
}
__device__ __forceinline__ float wredmax(float v){
    #pragma unroll
    for (int o = 16; o; o >>= 1) v = fmaxf(v, __shfl_down_sync(0xffffffffu, v, o));
    return v;
}
__device__ __forceinline__ float blockRedSum256(float v, float* red){
    int lane = threadIdx.x & 31, w = threadIdx.x >> 5;
    v = wredsum(v);
    if (lane == 0) red[w] = v;
    __syncthreads();
    if (threadIdx.x == 0){
        float s = 0.f;
        #pragma unroll
        for (int i = 0; i < 8; i++) s += red[i];
        red[0] = s;
    }
    __syncthreads();
    float r = red[0];
    __syncthreads();
    return r;
}
__device__ __forceinline__ float blockRedMax256(float v, float* red){
    int lane = threadIdx.x & 31, w = threadIdx.x >> 5;
    v = wredmax(v);
    if (lane == 0) red[w] = v;
    __syncthreads();
    if (threadIdx.x == 0){
        float s = red[0];
        #pragma unroll
        for (int i = 1; i < 8; i++) s = fmaxf(s, red[i]);
        red[0] = s;
    }
    __syncthreads();
    float r = red[0];
    __syncthreads();
    return r;
}

#define FMA2(d,a,b) asm("fma.rn.f32x2 %0, %1, %2, %0;" : "+l"(d) : "l"(a), "l"(b))
__device__ __forceinline__ float2 up2(unsigned long long v){
    float2 r; asm("mov.b64 {%0, %1}, %2;" : "=f"(r.x), "=f"(r.y) : "l"(v)); return r;
}
__device__ __forceinline__ int lidx(int c, int t){
    return (((t>>1)*257 + (c>>1))<<2) + ((t&1)<<1) + (c&1);
}
__device__ __forceinline__ void stcs2(float* p, float2 v){
    asm volatile("st.global.cs.v2.f32 [%0], {%1, %2};" :: "l"(p), "f"(v.x), "f"(v.y) : "memory");
}

// ---------------- K1a: per-(b,c) row sums ----------------
__global__ void k_rowsum(const float* __restrict__ v){
    int w = (blockIdx.x * blockDim.x + threadIdx.x) >> 5;
    int lane = threadIdx.x & 31;
    if (w >= BB*CC) return;
    const float4* row = (const float4*)(v + (size_t)w * HW);
    float p = 0.f, q = 0.f;
    #pragma unroll
    for (int i = 0; i < 7; i++){
        int idx = lane + i*32;
        if (idx < 196){
            float4 x = row[idx];
            p += x.x + x.y + x.z + x.w;
            q += x.x*x.x + x.y*x.y + x.z*x.z + x.w*x.w;
        }
    }
    p = wredsum(p); q = wredsum(q);
    if (lane == 0){ g_rowsum[w] = p; g_rowsq[w] = q; }
}

// ---------------- K1b: BN scale/shift (blocks 0..511) + a1 l2norm (blocks 512..575) ----------------
__global__ void k_prep(const float* __restrict__ gamma, const float* __restrict__ beta,
                       const float* __restrict__ t){
    int tid = threadIdx.x;  // 128
    if (blockIdx.x < CC){
        int c = blockIdx.x;
        __shared__ float sp[BB], sq[BB];
        if (tid < BB){
            sp[tid] = g_rowsum[tid*CC + c];
            sq[tid] = g_rowsq [tid*CC + c];
        }
        __syncthreads();
        if (tid == 0){
            float P = 0.f, Q = 0.f;
            for (int i = 0; i < BB; i++){ P += sp[i]; Q += sq[i]; }
            const float inv = 1.0f / (float)(BB*HW);
            float mu  = P * inv;
            float var = Q * inv - mu*mu;
            float sc  = gamma[c] * rsqrtf(var + 1e-5f);
            g_scale[c] = sc;
            g_shift[c] = beta[c] - mu * sc;
        }
    } else {
        int b = blockIdx.x - CC;
        float s = 0.f;
        for (int c = tid; c < CC; c += 128){ float x = t[b*CC + c]; s += x*x; }
        __shared__ float red[4];
        __shared__ float sinv;
        float ws = wredsum(s);
        if ((tid & 31) == 0) red[tid >> 5] = ws;
        __syncthreads();
        if (tid == 0) sinv = 1.0f / fmaxf(sqrtf(red[0]+red[1]+red[2]+red[3]), 1e-12f);
        __syncthreads();
        for (int c = tid; c < CC; c += 128) g_a1[b*CC + c] = t[b*CC + c] * sinv;
    }
}

// ---------------- K3: fused main pass ----------------
// 448 threads. kq = tid/112 (K quarter, warp-coherent); r = tid%112;
// tn = r/14 -> 8 n-rows; tt = r%14 -> pixels {2tt, 2tt+1, 2tt+28, 2tt+29}.
__global__ void __launch_bounds__(GT) k_main(
    const float* __restrict__ v,
    const float* __restrict__ w,
    const float* __restrict__ wb)
{
    extern __shared__ float Xs[];
    __shared__ float pr[8*TT], pa[8*TT], satt[TT], sinv[TT];
    __shared__ float pn[8*TT];
    __shared__ float stile[NREG*NTILE];

    int b    = blockIdx.x / NTILE;
    int tile = blockIdx.x % NTILE;
    int hw0  = tile * TT;
    int tid  = threadIdx.x;

    // ---- fill Xs + fused norm/att partials ----
    {
        int t  = tid % TT;
        int c0 = tid / TT;                  // 0..7
        const float* base = v + (size_t)b*CC*HW + hw0 + t;
        const float* a1b  = g_a1 + b*CC;
        float nr = 0.f, ad = 0.f;
        int fx = lidx(c0, t);               // step of c by 8 -> fidx += 16
        #pragma unroll 8
        for (int c = c0; c < CC; c += 8){
            float x = base[(size_t)c*HW] * g_scale[c] + g_shift[c];
            Xs[fx] = x;
            fx += 16;
            nr = fmaf(x, x, nr);
            ad = fmaf(x, a1b[c], ad);
        }
        pr[c0*TT + t] = nr;
        pa[c0*TT + t] = ad;
    }
    __syncthreads();
    if (tid < TT){
        float nr = 0.f, ad = 0.f;
        #pragma unroll
        for (int s = 0; s < 8; s++){ nr += pr[s*TT + tid]; ad += pa[s*TT + tid]; }
        float a = ad / fmaxf(sqrtf(nr), 1e-12f);
        satt[tid] = a;
        g_att2[b*HW + hw0 + tid] = a;
    }

    // ---- GEMM ----
    int kq = tid / 112;
    int r  = tid % 112;
    int tn = r / NTILE;          // 0..7
    int tt = r % NTILE;          // 0..13
    int n0 = tn*8;
    int p0 = 2*tt;               // first pixel; second group at p0+28

    unsigned long long acc[8][4];
    #pragma unroll
    for (int i = 0; i < 8; i++)
        #pragma unroll
        for (int j = 0; j < 4; j++) acc[i][j] = 0ull;

    {
        const ulonglong2* wp = (const ulonglong2*)w + n0*128 + kq*32;
        int s = (tt*257 + kq*64) << 2;       // float index of unit (pair tt, k2=kq*64)

        #pragma unroll 1
        for (int k4 = 0; k4 < 32; k4++){
            ulonglong2 xa0 = *(const ulonglong2*)(Xs + s);             // pair tt,   k2
            ulonglong2 xa1 = *(const ulonglong2*)(Xs + s + 4);         // pair tt,   k2+1
            ulonglong2 xb0 = *(const ulonglong2*)(Xs + s + OFF14);     // pair tt+14,k2
            ulonglong2 xb1 = *(const ulonglong2*)(Xs + s + OFF14 + 4); // pair tt+14,k2+1
            s += 8;

            {
                ulonglong2 wv0 = wp[k4 + 0*128];
                ulonglong2 wv1 = wp[k4 + 1*128];
                ulonglong2 wv2 = wp[k4 + 2*128];
                ulonglong2 wv3 = wp[k4 + 3*128];
                FMA2(acc[0][0], wv0.x, xa0.x); FMA2(acc[0][1], wv0.x, xa0.y);
                FMA2(acc[0][2], wv0.x, xb0.x); FMA2(acc[0][3], wv0.x, xb0.y);
                FMA2(acc[0][0], wv0.y, xa1.x); FMA2(acc[0][1], wv0.y, xa1.y);
                FMA2(acc[0][2], wv0.y, xb1.x); FMA2(acc[0][3], wv0.y, xb1.y);
                FMA2(acc[1][0], wv1.x, xa0.x); FMA2(acc[1][1], wv1.x, xa0.y);
                FMA2(acc[1][2], wv1.x, xb0.x); FMA2(acc[1][3], wv1.x, xb0.y);
                FMA2(acc[1][0], wv1.y, xa1.x); FMA2(acc[1][1], wv1.y, xa1.y);
                FMA2(acc[1][2], wv1.y, xb1.x); FMA2(acc[1][3], wv1.y, xb1.y);
                FMA2(acc[2][0], wv2.x, xa0.x); FMA2(acc[2][1], wv2.x, xa0.y);
                FMA2(acc[2][2], wv2.x, xb0.x); FMA2(acc[2][3], wv2.x, xb0.y);
                FMA2(acc[2][0], wv2.y, xa1.x); FMA2(acc[2][1], wv2.y, xa1.y);
                FMA2(acc[2][2], wv2.y, xb1.x); FMA2(acc[2][3], wv2.y, xb1.y);
                FMA2(acc[3][0], wv3.x, xa0.x); FMA2(acc[3][1], wv3.x, xa0.y);
                FMA2(acc[3][2], wv3.x, xb0.x); FMA2(acc[3][3], wv3.x, xb0.y);
                FMA2(acc[3][0], wv3.y, xa1.x); FMA2(acc[3][1], wv3.y, xa1.y);
                FMA2(acc[3][2], wv3.y, xb1.x); FMA2(acc[3][3], wv3.y, xb1.y);
            }
            {
                ulonglong2 wv4 = wp[k4 + 4*128];
                ulonglong2 wv5 = wp[k4 + 5*128];
                ulonglong2 wv6 = wp[k4 + 6*128];
                ulonglong2 wv7 = wp[k4 + 7*128];
                FMA2(acc[4][0], wv4.x, xa0.x); FMA2(acc[4][1], wv4.x, xa0.y);
                FMA2(acc[4][2], wv4.x, xb0.x); FMA2(acc[4][3], wv4.x, xb0.y);
                FMA2(acc[4][0], wv4.y, xa1.x); FMA2(acc[4][1], wv4.y, xa1.y);
                FMA2(acc[4][2], wv4.y, xb1.x); FMA2(acc[4][3], wv4.y, xb1.y);
                FMA2(acc[5][0], wv5.x, xa0.x); FMA2(acc[5][1], wv5.x, xa0.y);
                FMA2(acc[5][2], wv5.x, xb0.x); FMA2(acc[5][3], wv5.x, xb0.y);
                FMA2(acc[5][0], wv5.y, xa1.x); FMA2(acc[5][1], wv5.y, xa1.y);
                FMA2(acc[5][2], wv5.y, xb1.x); FMA2(acc[5][3], wv5.y, xb1.y);
                FMA2(acc[6][0], wv6.x, xa0.x); FMA2(acc[6][1], wv6.x, xa0.y);
                FMA2(acc[6][2], wv6.x, xb0.x); FMA2(acc[6][3], wv6.x, xb0.y);
                FMA2(acc[6][0], wv6.y, xa1.x); FMA2(acc[6][1], wv6.y, xa1.y);
                FMA2(acc[6][2], wv6.y, xb1.x); FMA2(acc[6][3], wv6.y, xb1.y);
                FMA2(acc[7][0], wv7.x, xa0.x); FMA2(acc[7][1], wv7.x, xa0.y);
                FMA2(acc[7][2], wv7.x, xb0.x); FMA2(acc[7][3], wv7.x, xb0.y);
                FMA2(acc[7][0], wv7.y, xa1.x); FMA2(acc[7][1], wv7.y, xa1.y);
                FMA2(acc[7][2], wv7.y, xb1.x); FMA2(acc[7][3], wv7.y, xb1.y);
            }
        }
    }

    // ---- combine K quarters, normalize, store ----
    __syncthreads();                        // all GEMM reads of Xs done
    float* comb = Xs;                       // 3 * [64][56] partials

    float sres[8][4];
    #pragma unroll
    for (int i = 0; i < 8; i++)
        #pragma unroll
        for (int j = 0; j < 4; j++){
            float2 f = up2(acc[i][j]);
            sres[i][j] = f.x + f.y;
        }

    if (kq){
        float* cb = comb + (kq-1)*NREG*TT;
        #pragma unroll
        for (int i = 0; i < 8; i++){
            int rw = (n0+i)*TT;
            *(float2*)&cb[rw + p0]      = make_float2(sres[i][0], sres[i][1]);
            *(float2*)&cb[rw + p0 + 28] = make_float2(sres[i][2], sres[i][3]);
        }
    }
    __syncthreads();
    if (kq == 0){
        #pragma unroll
        for (int i = 0; i < 8; i++){
            float bi = wb[n0+i];
            int rw = (n0+i)*TT;
            sres[i][0] += comb[rw+p0]    + comb[NREG*TT + rw+p0]    + comb[2*NREG*TT + rw+p0]    + bi;
            sres[i][1] += comb[rw+p0+1]  + comb[NREG*TT + rw+p0+1]  + comb[2*NREG*TT + rw+p0+1]  + bi;
            sres[i][2] += comb[rw+p0+28] + comb[NREG*TT + rw+p0+28] + comb[2*NREG*TT + rw+p0+28] + bi;
            sres[i][3] += comb[rw+p0+29] + comb[NREG*TT + rw+p0+29] + comb[2*NREG*TT + rw+p0+29] + bi;
        }
        float ss0 = 0.f, ss1 = 0.f, ss2 = 0.f, ss3 = 0.f;
        #pragma unroll
        for (int i = 0; i < 8; i++){
            ss0 = fmaf(sres[i][0], sres[i][0], ss0);
            ss1 = fmaf(sres[i][1], sres[i][1], ss1);
            ss2 = fmaf(sres[i][2], sres[i][2], ss2);
            ss3 = fmaf(sres[i][3], sres[i][3], ss3);
        }
        *(float2*)&pn[tn*TT + p0]      = make_float2(ss0, ss1);
        *(float2*)&pn[tn*TT + p0 + 28] = make_float2(ss2, ss3);
    }
    __syncthreads();
    if (tid < TT){
        float ss = 0.f;
        #pragma unroll
        for (int g = 0; g < 8; g++) ss += pn[g*TT + tid];
        sinv[tid] = 1.0f / fmaxf(sqrtf(ss), 1e-12f);
    }
    __syncthreads();
    if (kq == 0){
        float* outb = g_srean + ((size_t)b*NREG)*HW + hw0;
        float a0 = satt[p0], a1v = satt[p0+1], a2 = satt[p0+28], a3 = satt[p0+29];
        float i0 = sinv[p0], i1 = sinv[p0+1], i2 = sinv[p0+28], i3 = sinv[p0+29];
        #pragma unroll
        for (int i = 0; i < 8; i++){
            float o0 = sres[i][0]*i0, o1 = sres[i][1]*i1;
            float o2 = sres[i][2]*i2, o3 = sres[i][3]*i3;
            float* orow = outb + (size_t)(n0+i)*HW;
            stcs2(&orow[p0],      make_float2(o0, o1));
            stcs2(&orow[p0 + 28], make_float2(o2, o3));
            stile[(n0+i)*NTILE + tt] = o0*a0 + o1*a1v + o2*a2 + o3*a3;
        }
    }
    __syncthreads();
    if (tid < NREG){
        float q = 0.f;
        #pragma unroll
        for (int tl = 0; tl < NTILE; tl++) q += stile[tid*NTILE + tl];
        g_scorep[(b*NTILE + tile)*NREG + tid] = q;
    }
}

// ---------------- K5: feat = pooled @ fc1_w^T + fc1_b ----------------
#define PS 513
__global__ void k_feat(const float* __restrict__ fw, const float* __restrict__ fb){
    extern __shared__ float sm[];
    float* pooled = sm;
    float* ws     = sm + BB*PS;
    int tid = threadIdx.x;           // 256
    int o0 = blockIdx.x * 8;

    for (int idx = tid; idx < BB*CC; idx += 256){
        int bb = idx >> 9, cc = idx & 511;
        pooled[bb*PS + cc] = g_rowsum[idx] * (1.0f/(float)HW) * g_scale[cc] + g_shift[cc];
    }
    for (int idx = tid; idx < 8*CC; idx += 256){
        int oo = idx >> 9, cc = idx & 511;
        ws[oo*PS + cc] = fw[(size_t)(o0+oo)*CC + cc];
    }
    __syncthreads();

    #pragma unroll
    for (int rr = 0; rr < 2; rr++){
        int p  = tid*2 + rr;
        int bb = p >> 3, oo = p & 7;
        float s = 0.f;
        #pragma unroll 8
        for (int k = 0; k < CC; k++) s = fmaf(pooled[bb*PS + k], ws[oo*PS + k], s);
        g_feat[bb*CC + (o0+oo)] = s + fb[o0+oo];
    }
}

// ---------------- K6: per-batch stats + loss terms ----------------
__global__ void k_loss(){
    int b = blockIdx.x; int tid = threadIdx.x;  // 256
    __shared__ float ssc[NREG];
    __shared__ int s_nmax;
    __shared__ float red[8];
    if (tid < NREG){
        float sv = 0.f;
        #pragma unroll
        for (int tl = 0; tl < NTILE; tl++) sv += g_scorep[(b*NTILE + tl)*NREG + tid];
        ssc[tid] = sv;
    }
    __syncthreads();
    if (tid == 0){
        float m = 0.f;
        for (int n = 0; n < NREG; n++) m += ssc[n];
        m *= (1.0f/NREG);
        float bmax = ssc[0]; int imax = 0;
        float sp = 0.f, sq = 0.f;
        for (int n = 0; n < NREG; n++){
            float x = ssc[n];
            if (x > bmax){ bmax = x; imax = n; }
            if (x > m) sp += x; else sq += x;
        }
        sp *= (1.0f/NREG); sq *= (1.0f/NREG);
        float d = sq - sp;
        g_l3[b] = (d > 20.0f) ? d : log1pf(expf(d));
        s_nmax = imax;
    }
    __syncthreads();

    const float* pl = g_att2 + b*HW;
    const float* ql = g_srean + ((size_t)b*NREG + s_nmax)*HW;
    const float qs = 1.0f/(float)NREG;

    float mp = -1e30f, mq = -1e30f;
    for (int h = tid; h < HW; h += 256){
        mp = fmaxf(mp, pl[h]);
        mq = fmaxf(mq, ql[h]*qs);
    }
    mp = blockRedMax256(mp, red);
    mq = blockRedMax256(mq, red);

    float ep = 0.f, eq = 0.f;
    for (int h = tid; h < HW; h += 256){
        ep += expf(pl[h] - mp);
        eq += expf(ql[h]*qs - mq);
    }
    ep = blockRedSum256(ep, red);
    eq = blockRedSum256(eq, red);
    float lsep = mp + logf(ep);
    float lseq = mq + logf(eq);

    float S = 0.f;
    for (int h = tid; h < HW; h += 256){
        float lp = pl[h] - lsep;
        float lq = ql[h]*qs - lseq;
        float p  = expf(lp);
        float q  = expf(lq);
        float lm = logf(0.5f*(p + q));
        S += p*(lp - lm) + q*(lq - lm);
    }
    S = blockRedSum256(S, red);
    if (tid == 0) g_ls[b] = S;
}

// ---------------- K7: dual_sim ----------------
__global__ void k_dual(float* __restrict__ out){
    int b = blockIdx.x; int tid = threadIdx.x;  // 128
    __shared__ float fr[CC];
    __shared__ float red[4];
    __shared__ float sinvb;
    float ss = 0.f;
    for (int c = tid; c < CC; c += 128){ float x = g_feat[b*CC + c]; fr[c] = x; ss += x*x; }
    ss = wredsum(ss);
    if ((tid & 31) == 0) red[tid >> 5] = ss;
    __syncthreads();
    if (tid == 0) sinvb = 1.0f / fmaxf(sqrtf(red[0]+red[1]+red[2]+red[3]), 1e-12f);
    __syncthreads();
    int warp = tid >> 5, lane = tid & 31;
    for (int j = warp; j < BB; j += 4){
        const float* a = g_a1 + j*CC;
        float s = 0.f;
        for (int c = lane; c < CC; c += 32) s += fr[c] * a[c];
        s = wredsum(s);
        if (lane == 0) out[b*BB + j] = s * sinvb;
    }
}

// ---------------- K8: final scalar ----------------
__global__ void k_final(float* __restrict__ out, int li){
    int t = threadIdx.x;  // 64
    __shared__ float r3[BB], rls[BB];
    r3[t] = g_l3[t]; rls[t] = g_ls[t];
    __syncthreads();
    if (t == 0){
        float a = 0.f, c2 = 0.f;
        for (int i = 0; i < BB; i++){ a += r3[i]; c2 += rls[i]; }
        float loss3 = a / (float)BB;
        float loss2 = 0.5f * c2 / (float)BB;
        out[li] = 0.1f*loss3 + 0.1f*loss2;
    }
}

// ---------------- launcher ----------------
extern "C" void kernel_launch(void* const* d_in, const int* in_sizes, int n_in,
                              void* d_out, int out_size){
    const float* v     = (const float*)d_in[0];
    const float* t     = (const float*)d_in[1];
    const float* cw    = (const float*)d_in[2];
    const float* cb    = (const float*)d_in[3];
    const float* gamma = (const float*)d_in[4];
    const float* beta  = (const float*)d_in[5];
    const float* fw    = (const float*)d_in[6];
    const float* fb    = (const float*)d_in[7];
    float* out = (float*)d_out;

    cudaFuncSetAttribute(k_main, cudaFuncAttributeMaxDynamicSharedMemorySize, XS_BYTES);
    cudaFuncSetAttribute(k_feat, cudaFuncAttributeMaxDynamicSharedMemorySize, (BB*PS + 8*PS)*4);

    k_rowsum<<<(BB*CC)/8, 256>>>(v);
    k_prep<<<CC + BB, 128>>>(gamma, beta, t);
    k_main<<<BB*NTILE, GT, XS_BYTES>>>(v, cw, cb);
    k_feat<<<64, 256, (BB*PS + 8*PS)*4>>>(fw, fb);
    k_loss<<<BB, 256>>>();
    k_dual<<<BB, 128>>>(out);
    int li = (out_size > 4096) ? 4096 : (out_size - 1);
    k_final<<<1, 64>>>(out, li);
}

// round 8
// speedup vs baseline: 2.0841x; 1.1759x over previous
#include <cuda_runtime.h>
#include <math.h>

#define BB   64
#define CC   512
#define HW   784
#define NREG 64
#define TT   56
#define NTILE 14
#define GT   448
// X layout: 16B unit u = tp*257 + k2  (tp = pixel pair 0..27, k2 = K pair 0..255)
// float idx = 4u + (t&1)*2 + (c&1).
// Prefetch overrun bound: worst read is pair 27, k2=256, +1 unit ->
// fidx (27*257+256)*4 + 4 .. +7 = 28784..28787. Pad to 28800.
#define XS_FLOATS 28800
#define XS_BYTES  (XS_FLOATS*4)
#define OFF14     (14*257*4)

// ---------------- scratch ----------------
__device__ __align__(256) float g_scale[CC];
__device__ __align__(256) float g_shift[CC];
__device__ __align__(256) float g_rowsum[BB*CC];
__device__ __align__(256) float g_rowsq [BB*CC];
__device__ __align__(256) float g_a1   [BB*CC];
__device__ __align__(256) float g_pooled[BB*CC];
__device__ __align__(256) float g_att2 [BB*HW];
__device__ __align__(256) float g_srean[(size_t)BB*NREG*HW];
__device__ __align__(256) float g_scorep[BB*NTILE*NREG];
__device__ __align__(256) float g_featp[4*BB*CC];
__device__ __align__(256) float g_l3[BB];
__device__ __align__(256) float g_ls[BB];

// ---------------- helpers ----------------
__device__ __forceinline__ float wredsum(float v){
    #pragma unroll
    for (int o = 16; o; o >>= 1) v += __shfl_down_sync(0xffffffffu, v, o);
    return v;
}
__device__ __forceinline__ float wredmax(float v){
    #pragma unroll
    for (int o = 16; o; o >>= 1) v = fmaxf(v, __shfl_down_sync(0xffffffffu, v, o));
    return v;
}
__device__ __forceinline__ float blockRedSum256(float v, float* red){
    int lane = threadIdx.x & 31, w = threadIdx.x >> 5;
    v = wredsum(v);
    if (lane == 0) red[w] = v;
    __syncthreads();
    if (threadIdx.x == 0){
        float s = 0.f;
        #pragma unroll
        for (int i = 0; i < 8; i++) s += red[i];
        red[0] = s;
    }
    __syncthreads();
    float r = red[0];
    __syncthreads();
    return r;
}
__device__ __forceinline__ float blockRedMax256(float v, float* red){
    int lane = threadIdx.x & 31, w = threadIdx.x >> 5;
    v = wredmax(v);
    if (lane == 0) red[w] = v;
    __syncthreads();
    if (threadIdx.x == 0){
        float s = red[0];
        #pragma unroll
        for (int i = 1; i < 8; i++) s = fmaxf(s, red[i]);
        red[0] = s;
    }
    __syncthreads();
    float r = red[0];
    __syncthreads();
    return r;
}

#define FMA2(d,a,b) asm("fma.rn.f32x2 %0, %1, %2, %0;" : "+l"(d) : "l"(a), "l"(b))
__device__ __forceinline__ float2 up2(unsigned long long v){
    float2 r; asm("mov.b64 {%0, %1}, %2;" : "=f"(r.x), "=f"(r.y) : "l"(v)); return r;
}
__device__ __forceinline__ int lidx(int c, int t){
    return (((t>>1)*257 + (c>>1))<<2) + ((t&1)<<1) + (c&1);
}
__device__ __forceinline__ void stcs2(float* p, float2 v){
    asm volatile("st.global.cs.v2.f32 [%0], {%1, %2};" :: "l"(p), "f"(v.x), "f"(v.y) : "memory");
}

// ---------------- K1a: per-(b,c) row sums ----------------
__global__ void k_rowsum(const float* __restrict__ v){
    int w = (blockIdx.x * blockDim.x + threadIdx.x) >> 5;
    int lane = threadIdx.x & 31;
    if (w >= BB*CC) return;
    const float4* row = (const float4*)(v + (size_t)w * HW);
    float p = 0.f, q = 0.f;
    #pragma unroll
    for (int i = 0; i < 7; i++){
        int idx = lane + i*32;
        if (idx < 196){
            float4 x = row[idx];
            p += x.x + x.y + x.z + x.w;
            q += x.x*x.x + x.y*x.y + x.z*x.z + x.w*x.w;
        }
    }
    p = wredsum(p); q = wredsum(q);
    if (lane == 0){ g_rowsum[w] = p; g_rowsq[w] = q; }
}

// ---------------- K1b: BN params + pooled (blocks 0..511); a1 l2norm (512..575) ----------------
__global__ void k_prep(const float* __restrict__ gamma, const float* __restrict__ beta,
                       const float* __restrict__ t){
    int tid = threadIdx.x;  // 128
    if (blockIdx.x < CC){
        int c = blockIdx.x;
        __shared__ float sp[BB], sq[BB];
        __shared__ float ssc, ssh;
        if (tid < BB){
            sp[tid] = g_rowsum[tid*CC + c];
            sq[tid] = g_rowsq [tid*CC + c];
        }
        __syncthreads();
        if (tid == 0){
            float P = 0.f, Q = 0.f;
            for (int i = 0; i < BB; i++){ P += sp[i]; Q += sq[i]; }
            const float inv = 1.0f / (float)(BB*HW);
            float mu  = P * inv;
            float var = Q * inv - mu*mu;
            float sc  = gamma[c] * rsqrtf(var + 1e-5f);
            float sh  = beta[c] - mu * sc;
            g_scale[c] = sc;
            g_shift[c] = sh;
            ssc = sc; ssh = sh;
        }
        __syncthreads();
        if (tid < BB)
            g_pooled[tid*CC + c] = sp[tid] * (1.0f/(float)HW) * ssc + ssh;
    } else {
        int b = blockIdx.x - CC;
        float s = 0.f;
        for (int c = tid; c < CC; c += 128){ float x = t[b*CC + c]; s += x*x; }
        __shared__ float red[4];
        __shared__ float sinv;
        float ws = wredsum(s);
        if ((tid & 31) == 0) red[tid >> 5] = ws;
        __syncthreads();
        if (tid == 0) sinv = 1.0f / fmaxf(sqrtf(red[0]+red[1]+red[2]+red[3]), 1e-12f);
        __syncthreads();
        for (int c = tid; c < CC; c += 128) g_a1[b*CC + c] = t[b*CC + c] * sinv;
    }
}

// ---------------- K3: fused main pass ----------------
__global__ void __launch_bounds__(GT) k_main(
    const float* __restrict__ v,
    const float* __restrict__ w,
    const float* __restrict__ wb)
{
    extern __shared__ float Xs[];
    __shared__ float pr[8*TT], pa[8*TT], satt[TT], sinv[TT];
    __shared__ float pn[8*TT];
    __shared__ float stile[NREG*NTILE];

    int b    = blockIdx.x / NTILE;
    int tile = blockIdx.x % NTILE;
    int hw0  = tile * TT;
    int tid  = threadIdx.x;

    // ---- fill Xs + fused norm/att partials ----
    {
        int t  = tid % TT;
        int c0 = tid / TT;                  // 0..7
        const float* base = v + (size_t)b*CC*HW + hw0 + t;
        const float* a1b  = g_a1 + b*CC;
        float nr = 0.f, ad = 0.f;
        int fx = lidx(c0, t);
        #pragma unroll 8
        for (int c = c0; c < CC; c += 8){
            float x = base[(size_t)c*HW] * g_scale[c] + g_shift[c];
            Xs[fx] = x;
            fx += 16;
            nr = fmaf(x, x, nr);
            ad = fmaf(x, a1b[c], ad);
        }
        pr[c0*TT + t] = nr;
        pa[c0*TT + t] = ad;
    }
    __syncthreads();
    if (tid < TT){
        float nr = 0.f, ad = 0.f;
        #pragma unroll
        for (int s = 0; s < 8; s++){ nr += pr[s*TT + tid]; ad += pa[s*TT + tid]; }
        float a = ad / fmaxf(sqrtf(nr), 1e-12f);
        satt[tid] = a;
        g_att2[b*HW + hw0 + tid] = a;
    }

    // ---- GEMM: kq=tid/112, r=tid%112, tn=r/14 (8 n-rows), tt=r%14 (px pairs tt, tt+14) ----
    int kq = tid / 112;
    int r  = tid % 112;
    int tn = r / NTILE;
    int tt = r % NTILE;
    int n0 = tn*8;
    int p0 = 2*tt;

    unsigned long long acc[8][4];
    #pragma unroll
    for (int i = 0; i < 8; i++)
        #pragma unroll
        for (int j = 0; j < 4; j++) acc[i][j] = 0ull;

    {
        const ulonglong2* wp = (const ulonglong2*)w + n0*128 + kq*32;
        int s = (tt*257 + kq*64) << 2;

        // software pipeline: preload iter-0 X
        ulonglong2 xa0 = *(const ulonglong2*)(Xs + s);
        ulonglong2 xa1 = *(const ulonglong2*)(Xs + s + 4);
        ulonglong2 xb0 = *(const ulonglong2*)(Xs + s + OFF14);
        ulonglong2 xb1 = *(const ulonglong2*)(Xs + s + OFF14 + 4);

        #pragma unroll 1
        for (int k4 = 0; k4 < 32; k4++){
            s += 8;
            // prefetch next iteration's X (padding covers last-iter overrun)
            ulonglong2 na0 = *(const ulonglong2*)(Xs + s);
            ulonglong2 na1 = *(const ulonglong2*)(Xs + s + 4);
            ulonglong2 nb0 = *(const ulonglong2*)(Xs + s + OFF14);
            ulonglong2 nb1 = *(const ulonglong2*)(Xs + s + OFF14 + 4);

            {
                ulonglong2 wv0 = wp[k4 + 0*128];
                ulonglong2 wv1 = wp[k4 + 1*128];
                ulonglong2 wv2 = wp[k4 + 2*128];
                ulonglong2 wv3 = wp[k4 + 3*128];
                FMA2(acc[0][0], wv0.x, xa0.x); FMA2(acc[0][1], wv0.x, xa0.y);
                FMA2(acc[0][2], wv0.x, xb0.x); FMA2(acc[0][3], wv0.x, xb0.y);
                FMA2(acc[0][0], wv0.y, xa1.x); FMA2(acc[0][1], wv0.y, xa1.y);
                FMA2(acc[0][2], wv0.y, xb1.x); FMA2(acc[0][3], wv0.y, xb1.y);
                FMA2(acc[1][0], wv1.x, xa0.x); FMA2(acc[1][1], wv1.x, xa0.y);
                FMA2(acc[1][2], wv1.x, xb0.x); FMA2(acc[1][3], wv1.x, xb0.y);
                FMA2(acc[1][0], wv1.y, xa1.x); FMA2(acc[1][1], wv1.y, xa1.y);
                FMA2(acc[1][2], wv1.y, xb1.x); FMA2(acc[1][3], wv1.y, xb1.y);
                FMA2(acc[2][0], wv2.x, xa0.x); FMA2(acc[2][1], wv2.x, xa0.y);
                FMA2(acc[2][2], wv2.x, xb0.x); FMA2(acc[2][3], wv2.x, xb0.y);
                FMA2(acc[2][0], wv2.y, xa1.x); FMA2(acc[2][1], wv2.y, xa1.y);
                FMA2(acc[2][2], wv2.y, xb1.x); FMA2(acc[2][3], wv2.y, xb1.y);
                FMA2(acc[3][0], wv3.x, xa0.x); FMA2(acc[3][1], wv3.x, xa0.y);
                FMA2(acc[3][2], wv3.x, xb0.x); FMA2(acc[3][3], wv3.x, xb0.y);
                FMA2(acc[3][0], wv3.y, xa1.x); FMA2(acc[3][1], wv3.y, xa1.y);
                FMA2(acc[3][2], wv3.y, xb1.x); FMA2(acc[3][3], wv3.y, xb1.y);
            }
            {
                ulonglong2 wv4 = wp[k4 + 4*128];
                ulonglong2 wv5 = wp[k4 + 5*128];
                ulonglong2 wv6 = wp[k4 + 6*128];
                ulonglong2 wv7 = wp[k4 + 7*128];
                FMA2(acc[4][0], wv4.x, xa0.x); FMA2(acc[4][1], wv4.x, xa0.y);
                FMA2(acc[4][2], wv4.x, xb0.x); FMA2(acc[4][3], wv4.x, xb0.y);
                FMA2(acc[4][0], wv4.y, xa1.x); FMA2(acc[4][1], wv4.y, xa1.y);
                FMA2(acc[4][2], wv4.y, xb1.x); FMA2(acc[4][3], wv4.y, xb1.y);
                FMA2(acc[5][0], wv5.x, xa0.x); FMA2(acc[5][1], wv5.x, xa0.y);
                FMA2(acc[5][2], wv5.x, xb0.x); FMA2(acc[5][3], wv5.x, xb0.y);
                FMA2(acc[5][0], wv5.y, xa1.x); FMA2(acc[5][1], wv5.y, xa1.y);
                FMA2(acc[5][2], wv5.y, xb1.x); FMA2(acc[5][3], wv5.y, xb1.y);
                FMA2(acc[6][0], wv6.x, xa0.x); FMA2(acc[6][1], wv6.x, xa0.y);
                FMA2(acc[6][2], wv6.x, xb0.x); FMA2(acc[6][3], wv6.x, xb0.y);
                FMA2(acc[6][0], wv6.y, xa1.x); FMA2(acc[6][1], wv6.y, xa1.y);
                FMA2(acc[6][2], wv6.y, xb1.x); FMA2(acc[6][3], wv6.y, xb1.y);
                FMA2(acc[7][0], wv7.x, xa0.x); FMA2(acc[7][1], wv7.x, xa0.y);
                FMA2(acc[7][2], wv7.x, xb0.x); FMA2(acc[7][3], wv7.x, xb0.y);
                FMA2(acc[7][0], wv7.y, xa1.x); FMA2(acc[7][1], wv7.y, xa1.y);
                FMA2(acc[7][2], wv7.y, xb1.x); FMA2(acc[7][3], wv7.y, xb1.y);
            }
            xa0 = na0; xa1 = na1; xb0 = nb0; xb1 = nb1;
        }
    }

    // ---- combine K quarters, normalize, store ----
    __syncthreads();
    float* comb = Xs;

    float sres[8][4];
    #pragma unroll
    for (int i = 0; i < 8; i++)
        #pragma unroll
        for (int j = 0; j < 4; j++){
            float2 f = up2(acc[i][j]);
            sres[i][j] = f.x + f.y;
        }

    if (kq){
        float* cb = comb + (kq-1)*NREG*TT;
        #pragma unroll
        for (int i = 0; i < 8; i++){
            int rw = (n0+i)*TT;
            *(float2*)&cb[rw + p0]      = make_float2(sres[i][0], sres[i][1]);
            *(float2*)&cb[rw + p0 + 28] = make_float2(sres[i][2], sres[i][3]);
        }
    }
    __syncthreads();
    if (kq == 0){
        #pragma unroll
        for (int i = 0; i < 8; i++){
            float bi = wb[n0+i];
            int rw = (n0+i)*TT;
            sres[i][0] += comb[rw+p0]    + comb[NREG*TT + rw+p0]    + comb[2*NREG*TT + rw+p0]    + bi;
            sres[i][1] += comb[rw+p0+1]  + comb[NREG*TT + rw+p0+1]  + comb[2*NREG*TT + rw+p0+1]  + bi;
            sres[i][2] += comb[rw+p0+28] + comb[NREG*TT + rw+p0+28] + comb[2*NREG*TT + rw+p0+28] + bi;
            sres[i][3] += comb[rw+p0+29] + comb[NREG*TT + rw+p0+29] + comb[2*NREG*TT + rw+p0+29] + bi;
        }
        float ss0 = 0.f, ss1 = 0.f, ss2 = 0.f, ss3 = 0.f;
        #pragma unroll
        for (int i = 0; i < 8; i++){
            ss0 = fmaf(sres[i][0], sres[i][0], ss0);
            ss1 = fmaf(sres[i][1], sres[i][1], ss1);
            ss2 = fmaf(sres[i][2], sres[i][2], ss2);
            ss3 = fmaf(sres[i][3], sres[i][3], ss3);
        }
        *(float2*)&pn[tn*TT + p0]      = make_float2(ss0, ss1);
        *(float2*)&pn[tn*TT + p0 + 28] = make_float2(ss2, ss3);
    }
    __syncthreads();
    if (tid < TT){
        float ss = 0.f;
        #pragma unroll
        for (int g = 0; g < 8; g++) ss += pn[g*TT + tid];
        sinv[tid] = 1.0f / fmaxf(sqrtf(ss), 1e-12f);
    }
    __syncthreads();
    if (kq == 0){
        float* outb = g_srean + ((size_t)b*NREG)*HW + hw0;
        float a0 = satt[p0], a1v = satt[p0+1], a2 = satt[p0+28], a3 = satt[p0+29];
        float i0 = sinv[p0], i1 = sinv[p0+1], i2 = sinv[p0+28], i3 = sinv[p0+29];
        #pragma unroll
        for (int i = 0; i < 8; i++){
            float o0 = sres[i][0]*i0, o1 = sres[i][1]*i1;
            float o2 = sres[i][2]*i2, o3 = sres[i][3]*i3;
            float* orow = outb + (size_t)(n0+i)*HW;
            stcs2(&orow[p0],      make_float2(o0, o1));
            stcs2(&orow[p0 + 28], make_float2(o2, o3));
            stile[(n0+i)*NTILE + tt] = o0*a0 + o1*a1v + o2*a2 + o3*a3;
        }
    }
    __syncthreads();
    if (tid < NREG){
        float q = 0.f;
        #pragma unroll
        for (int tl = 0; tl < NTILE; tl++) q += stile[tid*NTILE + tl];
        g_scorep[(b*NTILE + tile)*NREG + tid] = q;
    }
}

// ---------------- K5: feat partials, split-K x4 ----------------
#define FPAD 129
__global__ void k_feat(const float* __restrict__ fw){
    __shared__ float pooled[BB*FPAD];
    __shared__ float ws[8*FPAD];
    int tid = threadIdx.x;            // 256
    int o0  = (blockIdx.x & 63) * 8;
    int q   = blockIdx.x >> 6;        // 0..3
    int c0  = q * 128;

    for (int idx = tid; idx < BB*128; idx += 256){
        int bb = idx >> 7, kk = idx & 127;
        pooled[bb*FPAD + kk] = g_pooled[bb*CC + c0 + kk];
    }
    for (int idx = tid; idx < 8*128; idx += 256){
        int oo = idx >> 7, kk = idx & 127;
        ws[oo*FPAD + kk] = fw[(size_t)(o0+oo)*CC + c0 + kk];
    }
    __syncthreads();

    #pragma unroll
    for (int rr = 0; rr < 2; rr++){
        int p  = tid*2 + rr;
        int bb = p >> 3, oo = p & 7;
        float s = 0.f;
        #pragma unroll 4
        for (int k = 0; k < 128; k++) s = fmaf(pooled[bb*FPAD + k], ws[oo*FPAD + k], s);
        g_featp[(q*BB + bb)*CC + o0 + oo] = s;
    }
}

// ---------------- K6: loss (blocks 0..63) + dual_sim (blocks 64..127) ----------------
__global__ void k_lossdual(const float* __restrict__ fb, float* __restrict__ out){
    int tid = threadIdx.x;  // 256
    if (blockIdx.x < BB){
        int b = blockIdx.x;
        __shared__ float ssc[NREG];
        __shared__ int s_nmax;
        __shared__ float red[8];
        if (tid < NREG){
            float sv = 0.f;
            #pragma unroll
            for (int tl = 0; tl < NTILE; tl++) sv += g_scorep[(b*NTILE + tl)*NREG + tid];
            ssc[tid] = sv;
        }
        __syncthreads();
        if (tid == 0){
            float m = 0.f;
            for (int n = 0; n < NREG; n++) m += ssc[n];
            m *= (1.0f/NREG);
            float bmax = ssc[0]; int imax = 0;
            float sp = 0.f, sq = 0.f;
            for (int n = 0; n < NREG; n++){
                float x = ssc[n];
                if (x > bmax){ bmax = x; imax = n; }
                if (x > m) sp += x; else sq += x;
            }
            sp *= (1.0f/NREG); sq *= (1.0f/NREG);
            float d = sq - sp;
            g_l3[b] = (d > 20.0f) ? d : log1pf(expf(d));
            s_nmax = imax;
        }
        __syncthreads();

        const float* pl = g_att2 + b*HW;
        const float* ql = g_srean + ((size_t)b*NREG + s_nmax)*HW;
        const float qs = 1.0f/(float)NREG;

        float mp = -1e30f, mq = -1e30f;
        for (int h = tid; h < HW; h += 256){
            mp = fmaxf(mp, pl[h]);
            mq = fmaxf(mq, ql[h]*qs);
        }
        mp = blockRedMax256(mp, red);
        mq = blockRedMax256(mq, red);

        float ep = 0.f, eq = 0.f;
        for (int h = tid; h < HW; h += 256){
            ep += expf(pl[h] - mp);
            eq += expf(ql[h]*qs - mq);
        }
        ep = blockRedSum256(ep, red);
        eq = blockRedSum256(eq, red);
        float lsep = mp + logf(ep);
        float lseq = mq + logf(eq);

        float S = 0.f;
        for (int h = tid; h < HW; h += 256){
            float lp = pl[h] - lsep;
            float lq = ql[h]*qs - lseq;
            float p  = expf(lp);
            float q  = expf(lq);
            float lm = logf(0.5f*(p + q));
            S += p*(lp - lm) + q*(lq - lm);
        }
        S = blockRedSum256(S, red);
        if (tid == 0) g_ls[b] = S;
    } else {
        int b = blockIdx.x - BB;
        __shared__ float fr[CC];
        __shared__ float red[8];
        __shared__ float sinvb;
        float ss = 0.f;
        for (int c = tid; c < CC; c += 256){
            float x = g_featp[b*CC + c] + g_featp[(BB + b)*CC + c]
                    + g_featp[(2*BB + b)*CC + c] + g_featp[(3*BB + b)*CC + c] + fb[c];
            fr[c] = x; ss += x*x;
        }
        ss = blockRedSum256(ss, red);
        if (tid == 0) sinvb = 1.0f / fmaxf(sqrtf(ss), 1e-12f);
        __syncthreads();
        int warp = tid >> 5, lane = tid & 31;
        for (int j = warp; j < BB; j += 8){
            const float* a = g_a1 + j*CC;
            float s = 0.f;
            for (int c = lane; c < CC; c += 32) s += fr[c] * a[c];
            s = wredsum(s);
            if (lane == 0) out[b*BB + j] = s * sinvb;
        }
    }
}

// ---------------- K8: final scalar ----------------
__global__ void k_final(float* __restrict__ out, int li){
    int t = threadIdx.x;  // 64
    __shared__ float r3[BB], rls[BB];
    r3[t] = g_l3[t]; rls[t] = g_ls[t];
    __syncthreads();
    if (t == 0){
        float a = 0.f, c2 = 0.f;
        for (int i = 0; i < BB; i++){ a += r3[i]; c2 += rls[i]; }
        float loss3 = a / (float)BB;
        float loss2 = 0.5f * c2 / (float)BB;
        out[li] = 0.1f*loss3 + 0.1f*loss2;
    }
}

// ---------------- launcher ----------------
extern "C" void kernel_launch(void* const* d_in, const int* in_sizes, int n_in,
                              void* d_out, int out_size){
    const float* v     = (const float*)d_in[0];
    const float* t     = (const float*)d_in[1];
    const float* cw    = (const float*)d_in[2];
    const float* cb    = (const float*)d_in[3];
    const float* gamma = (const float*)d_in[4];
    const float* beta  = (const float*)d_in[5];
    const float* fw    = (const float*)d_in[6];
    const float* fb    = (const float*)d_in[7];
    float* out = (float*)d_out;

    cudaFuncSetAttribute(k_main, cudaFuncAttributeMaxDynamicSharedMemorySize, XS_BYTES);

    k_rowsum<<<(BB*CC)/8, 256>>>(v);
    k_prep<<<CC + BB, 128>>>(gamma, beta, t);
    k_main<<<BB*NTILE, GT, XS_BYTES>>>(v, cw, cb);
    k_feat<<<256, 256>>>(fw);
    k_lossdual<<<2*BB, 256>>>(fb, out);
    int li = (out_size > 4096) ? 4096 : (out_size - 1);
    k_final<<<1, 64>>>(out, li);
}